// round 1
// baseline (speedup 1.0000x reference)
#include <cuda_runtime.h>
#include <cstddef>

#define BB 32
#define NN 2048
#define DD 128
#define HH 128
#define NEGV 9000000000000000.0f

// Scratch for q/k/v activations (allocation-free rule: static device arrays).
__device__ float g_q[BB * NN * HH];
__device__ float g_k[BB * NN * HH];
__device__ float g_v[BB * NN * HH];

// ---------- packed f32x2 helpers ----------
__device__ __forceinline__ unsigned long long pk2(float lo, float hi) {
    unsigned long long r;
    asm("mov.b64 %0, {%1, %2};" : "=l"(r) : "f"(lo), "f"(hi));
    return r;
}
__device__ __forceinline__ float2 upk2(unsigned long long p) {
    float2 f;
    asm("mov.b64 {%0, %1}, %2;" : "=f"(f.x), "=f"(f.y) : "l"(p));
    return f;
}
__device__ __forceinline__ unsigned long long f2fma(unsigned long long a,
                                                    unsigned long long b,
                                                    unsigned long long c) {
    unsigned long long d;
    asm("fma.rn.f32x2 %0, %1, %2, %3;" : "=l"(d) : "l"(a), "l"(b), "l"(c));
    return d;
}
__device__ __forceinline__ unsigned long long f2mul(unsigned long long a,
                                                    unsigned long long b) {
    unsigned long long d;
    asm("mul.rn.f32x2 %0, %1, %2;" : "=l"(d) : "l"(a), "l"(b));
    return d;
}

// ============================================================
// Kernel A: fused QKV projection, out = tanh(x @ W + b)
// grid (1024, 3), 256 threads. 64 rows x 128 cols per block.
// Thread tile: 4 rows x 8 cols (4 f32x2 col-pairs).
// smem: xs[64][128] + ws[32][128] (dynamic, 48KB)
// ============================================================
__global__ __launch_bounds__(256, 1) void proj_kernel(
    const float* __restrict__ x,
    const float* __restrict__ Wq, const float* __restrict__ bq,
    const float* __restrict__ Wk, const float* __restrict__ bk,
    const float* __restrict__ Wv, const float* __restrict__ bv) {
    extern __shared__ float sm[];
    float* xs = sm;              // 64*128
    float* ws = sm + 64 * 128;   // 32*128

    const float* W;
    const float* bias;
    float* outp;
    if (blockIdx.y == 0)      { W = Wq; bias = bq; outp = g_q; }
    else if (blockIdx.y == 1) { W = Wk; bias = bk; outp = g_k; }
    else                      { W = Wv; bias = bv; outp = g_v; }

    const int tid = threadIdx.x;
    const int rowg = tid >> 4;   // 0..15 -> rows rowg*4..+3
    const int colg = tid & 15;   // cols {colg*4..+3, 64+colg*4..+3}
    const int row0 = blockIdx.x * 64;

    // load x tile (linear copy, coalesced)
    {
        const float4* src = reinterpret_cast<const float4*>(x + (size_t)row0 * DD);
        float4* dst = reinterpret_cast<float4*>(xs);
#pragma unroll
        for (int t = 0; t < 8; t++) dst[tid + t * 256] = src[tid + t * 256];
    }

    unsigned long long acc[4][4];
#pragma unroll
    for (int r = 0; r < 4; r++)
#pragma unroll
        for (int c = 0; c < 4; c++) acc[r][c] = 0ull;

#pragma unroll 1
    for (int chunk = 0; chunk < 4; chunk++) {
        const int kk0 = chunk * 32;
        __syncthreads();
        {
            const float4* src = reinterpret_cast<const float4*>(W + (size_t)kk0 * HH);
            float4* dst = reinterpret_cast<float4*>(ws);
#pragma unroll
            for (int t = 0; t < 4; t++) dst[tid + t * 256] = src[tid + t * 256];
        }
        __syncthreads();

#pragma unroll 2
        for (int kkl = 0; kkl < 32; kkl++) {
            const int kk = kk0 + kkl;
            float xv[4];
#pragma unroll
            for (int r = 0; r < 4; r++) xv[r] = xs[(rowg * 4 + r) * DD + kk];
            float4 wa = *reinterpret_cast<const float4*>(ws + kkl * HH + colg * 4);
            float4 wb = *reinterpret_cast<const float4*>(ws + kkl * HH + 64 + colg * 4);
            unsigned long long wp[4];
            wp[0] = *reinterpret_cast<unsigned long long*>(&wa.x);
            wp[1] = *reinterpret_cast<unsigned long long*>(&wa.z);
            wp[2] = *reinterpret_cast<unsigned long long*>(&wb.x);
            wp[3] = *reinterpret_cast<unsigned long long*>(&wb.z);
#pragma unroll
            for (int r = 0; r < 4; r++) {
                unsigned long long xp = pk2(xv[r], xv[r]);
#pragma unroll
                for (int c = 0; c < 4; c++) acc[r][c] = f2fma(xp, wp[c], acc[r][c]);
            }
        }
    }

    float4 ba = *reinterpret_cast<const float4*>(bias + colg * 4);
    float4 bb = *reinterpret_cast<const float4*>(bias + 64 + colg * 4);
#pragma unroll
    for (int r = 0; r < 4; r++) {
        float2 a0 = upk2(acc[r][0]);
        float2 a1 = upk2(acc[r][1]);
        float2 a2 = upk2(acc[r][2]);
        float2 a3 = upk2(acc[r][3]);
        float4 oa, ob;
        oa.x = tanhf(a0.x + ba.x); oa.y = tanhf(a0.y + ba.y);
        oa.z = tanhf(a1.x + ba.z); oa.w = tanhf(a1.y + ba.w);
        ob.x = tanhf(a2.x + bb.x); ob.y = tanhf(a2.y + bb.y);
        ob.z = tanhf(a3.x + bb.z); ob.w = tanhf(a3.y + bb.w);
        float* orow = outp + (size_t)(row0 + rowg * 4 + r) * HH;
        *reinterpret_cast<float4*>(orow + colg * 4) = oa;
        *reinterpret_cast<float4*>(orow + 64 + colg * 4) = ob;
    }
}

// ============================================================
// Kernel B: fused masked-softmax attention (flash style)
// grid 512 (= 32 batches x 16 i-tiles of 128), 256 threads.
// smem (dynamic 192KB): Qt[128][128] kk-major, KP[128][128] (Kt then Pt),
//                       Vs[128][128] j-major.
// Thread tile: 8 i-rows x 8 j-cols (S) / 8 i-rows x 8 h-cols (O), f32x2 pairs.
// ============================================================
__device__ __forceinline__ void load_transpose(const float4* __restrict__ src,
                                               float* __restrict__ dst, int tid) {
    // src rows i: 0..127, 32 float4 each (kk); dst[kk*128 + i]
#pragma unroll
    for (int t = 0; t < 16; t++) {
        int idx = tid + t * 256;
        int i = idx >> 5;
        int kc = idx & 31;
        float4 v = src[i * 32 + kc];
        dst[(4 * kc + 0) * 128 + i] = v.x;
        dst[(4 * kc + 1) * 128 + i] = v.y;
        dst[(4 * kc + 2) * 128 + i] = v.z;
        dst[(4 * kc + 3) * 128 + i] = v.w;
    }
}

__global__ __launch_bounds__(256, 1) void attn_kernel(
    const float* __restrict__ mask, float* __restrict__ out) {
    extern __shared__ float sm[];
    float* Qt = sm;            // 16384 floats
    float* KP = sm + 16384;    // Kt (QK phase) then Pt (PV phase)
    float* Vs = sm + 32768;

    const int tid = threadIdx.x;
    const int rowg = tid >> 4;
    const int colg = tid & 15;
    const int b = blockIdx.x >> 4;
    const int i0 = (blockIdx.x & 15) << 7;

    load_transpose(reinterpret_cast<const float4*>(g_q + (size_t)(b * NN + i0) * HH),
                   Qt, tid);

    unsigned long long o[8][4];
#pragma unroll
    for (int r = 0; r < 8; r++)
#pragma unroll
        for (int c = 0; c < 4; c++) o[r][c] = 0ull;
    float mrow[8], lrow[8];
#pragma unroll
    for (int r = 0; r < 8; r++) { mrow[r] = -__int_as_float(0x7f800000); lrow[r] = 0.0f; }

#pragma unroll 1
    for (int jt = 0; jt < 16; jt++) {
        const int j0 = jt << 7;
        __syncthreads();  // prior Pt/Vs reads done (also covers Qt on jt=0)
        load_transpose(reinterpret_cast<const float4*>(g_k + (size_t)(b * NN + j0) * HH),
                       KP, tid);
        {
            const float4* src =
                reinterpret_cast<const float4*>(g_v + (size_t)(b * NN + j0) * HH);
            float4* dst = reinterpret_cast<float4*>(Vs);
#pragma unroll
            for (int t = 0; t < 16; t++) dst[tid + t * 256] = src[tid + t * 256];
        }
        __syncthreads();

        // ---- S = Q K^T (128x128 tile) ----
        unsigned long long sacc[8][4];
#pragma unroll
        for (int r = 0; r < 8; r++)
#pragma unroll
            for (int c = 0; c < 4; c++) sacc[r][c] = 0ull;

#pragma unroll 2
        for (int kk = 0; kk < 128; kk++) {
            float4 qa = *reinterpret_cast<const float4*>(Qt + kk * 128 + rowg * 4);
            float4 qb = *reinterpret_cast<const float4*>(Qt + kk * 128 + 64 + rowg * 4);
            float4 ka = *reinterpret_cast<const float4*>(KP + kk * 128 + colg * 4);
            float4 kb = *reinterpret_cast<const float4*>(KP + kk * 128 + 64 + colg * 4);
            unsigned long long kp[4];
            kp[0] = *reinterpret_cast<unsigned long long*>(&ka.x);
            kp[1] = *reinterpret_cast<unsigned long long*>(&ka.z);
            kp[2] = *reinterpret_cast<unsigned long long*>(&kb.x);
            kp[3] = *reinterpret_cast<unsigned long long*>(&kb.z);
            float qv[8] = {qa.x, qa.y, qa.z, qa.w, qb.x, qb.y, qb.z, qb.w};
#pragma unroll
            for (int r = 0; r < 8; r++) {
                unsigned long long qp = pk2(qv[r], qv[r]);
#pragma unroll
                for (int c = 0; c < 4; c++) sacc[r][c] = f2fma(qp, kp[c], sacc[r][c]);
            }
        }

        // ---- mask + online softmax ----
        float p[8][8];
#pragma unroll
        for (int r = 0; r < 8; r++) {
            float2 s0 = upk2(sacc[r][0]);
            float2 s1 = upk2(sacc[r][1]);
            float2 s2 = upk2(sacc[r][2]);
            float2 s3 = upk2(sacc[r][3]);
            p[r][0] = s0.x; p[r][1] = s0.y; p[r][2] = s1.x; p[r][3] = s1.y;
            p[r][4] = s2.x; p[r][5] = s2.y; p[r][6] = s3.x; p[r][7] = s3.y;
        }
#pragma unroll
        for (int r = 0; r < 8; r++) {
            const int ir = i0 + rowg * 4 + (r & 3) + ((r >> 2) << 6);
            const float4* mp = reinterpret_cast<const float4*>(
                mask + (size_t)(b * NN + ir) * NN + j0);
            float4 ma = mp[colg];
            float4 mb = mp[16 + colg];
            p[r][0] = (ma.x != 0.0f) ? p[r][0] : -NEGV;
            p[r][1] = (ma.y != 0.0f) ? p[r][1] : -NEGV;
            p[r][2] = (ma.z != 0.0f) ? p[r][2] : -NEGV;
            p[r][3] = (ma.w != 0.0f) ? p[r][3] : -NEGV;
            p[r][4] = (mb.x != 0.0f) ? p[r][4] : -NEGV;
            p[r][5] = (mb.y != 0.0f) ? p[r][5] : -NEGV;
            p[r][6] = (mb.z != 0.0f) ? p[r][6] : -NEGV;
            p[r][7] = (mb.w != 0.0f) ? p[r][7] : -NEGV;

            float tmax = p[r][0];
#pragma unroll
            for (int c = 1; c < 8; c++) tmax = fmaxf(tmax, p[r][c]);
#pragma unroll
            for (int w = 1; w < 16; w <<= 1)
                tmax = fmaxf(tmax, __shfl_xor_sync(0xffffffffu, tmax, w));

            float mnew = fmaxf(mrow[r], tmax);
            float corr = __expf(mrow[r] - mnew);
            float ps = 0.0f;
#pragma unroll
            for (int c = 0; c < 8; c++) {
                p[r][c] = __expf(p[r][c] - mnew);
                ps += p[r][c];
            }
#pragma unroll
            for (int w = 1; w < 16; w <<= 1)
                ps += __shfl_xor_sync(0xffffffffu, ps, w);
            lrow[r] = lrow[r] * corr + ps;
            mrow[r] = mnew;
            unsigned long long cp = pk2(corr, corr);
#pragma unroll
            for (int hc = 0; hc < 4; hc++) o[r][hc] = f2mul(o[r][hc], cp);
        }

        // ---- P -> smem (Pt[j][i]) reusing the Kt buffer ----
        __syncthreads();  // all warps finished reading Kt
#pragma unroll
        for (int r = 0; r < 8; r++) {
            const int irl = rowg * 4 + (r & 3) + ((r >> 2) << 6);
#pragma unroll
            for (int c = 0; c < 8; c++) {
                const int jl = colg * 4 + (c & 3) + ((c >> 2) << 6);
                KP[jl * 128 + irl] = p[r][c];
            }
        }
        __syncthreads();

        // ---- O += P V ----
#pragma unroll 2
        for (int jj = 0; jj < 128; jj++) {
            float4 pa = *reinterpret_cast<const float4*>(KP + jj * 128 + rowg * 4);
            float4 pb = *reinterpret_cast<const float4*>(KP + jj * 128 + 64 + rowg * 4);
            float4 va = *reinterpret_cast<const float4*>(Vs + jj * 128 + colg * 4);
            float4 vb = *reinterpret_cast<const float4*>(Vs + jj * 128 + 64 + colg * 4);
            unsigned long long vp[4];
            vp[0] = *reinterpret_cast<unsigned long long*>(&va.x);
            vp[1] = *reinterpret_cast<unsigned long long*>(&va.z);
            vp[2] = *reinterpret_cast<unsigned long long*>(&vb.x);
            vp[3] = *reinterpret_cast<unsigned long long*>(&vb.z);
            float pv[8] = {pa.x, pa.y, pa.z, pa.w, pb.x, pb.y, pb.z, pb.w};
#pragma unroll
            for (int r = 0; r < 8; r++) {
                unsigned long long pp = pk2(pv[r], pv[r]);
#pragma unroll
                for (int hc = 0; hc < 4; hc++) o[r][hc] = f2fma(pp, vp[hc], o[r][hc]);
            }
        }
    }

    // ---- epilogue: normalize and store ----
#pragma unroll
    for (int r = 0; r < 8; r++) {
        const int ir = i0 + rowg * 4 + (r & 3) + ((r >> 2) << 6);
        const float inv = 1.0f / lrow[r];
        float2 o0 = upk2(o[r][0]);
        float2 o1 = upk2(o[r][1]);
        float2 o2 = upk2(o[r][2]);
        float2 o3 = upk2(o[r][3]);
        float4 oa, ob;
        oa.x = o0.x * inv; oa.y = o0.y * inv; oa.z = o1.x * inv; oa.w = o1.y * inv;
        ob.x = o2.x * inv; ob.y = o2.y * inv; ob.z = o3.x * inv; ob.w = o3.y * inv;
        float* orow = out + (size_t)(b * NN + ir) * HH;
        *reinterpret_cast<float4*>(orow + colg * 4) = oa;
        *reinterpret_cast<float4*>(orow + 64 + colg * 4) = ob;
    }
}

extern "C" void kernel_launch(void* const* d_in, const int* in_sizes, int n_in,
                              void* d_out, int out_size) {
    const float* x    = (const float*)d_in[0];
    const float* mask = (const float*)d_in[1];
    const float* Wv   = (const float*)d_in[2];
    const float* bv   = (const float*)d_in[3];
    const float* Wk   = (const float*)d_in[4];
    const float* bk   = (const float*)d_in[5];
    const float* Wq   = (const float*)d_in[6];
    const float* bq   = (const float*)d_in[7];
    float* out = (float*)d_out;

    cudaFuncSetAttribute(proj_kernel, cudaFuncAttributeMaxDynamicSharedMemorySize,
                         49152);
    cudaFuncSetAttribute(attn_kernel, cudaFuncAttributeMaxDynamicSharedMemorySize,
                         196608);

    proj_kernel<<<dim3(1024, 3, 1), 256, 49152>>>(x, Wq, bq, Wk, bk, Wv, bv);
    attn_kernel<<<512, 256, 196608>>>(mask, out);
}

// round 3
// speedup vs baseline: 2.1185x; 2.1185x over previous
#include <cuda_runtime.h>
#include <cstdint>
#include <cstddef>

#define BB 32
#define NN 2048
#define DD 128
#define HH 128

// Scratch for q/k/v activations (allocation-free rule: static device arrays).
__device__ float g_q[BB * NN * HH];
__device__ float g_k[BB * NN * HH];
__device__ float g_v[BB * NN * HH];

// ---------- packed f32x2 helpers (projection kernel) ----------
__device__ __forceinline__ unsigned long long pk2(float lo, float hi) {
    unsigned long long r;
    asm("mov.b64 %0, {%1, %2};" : "=l"(r) : "f"(lo), "f"(hi));
    return r;
}
__device__ __forceinline__ float2 upk2(unsigned long long p) {
    float2 f;
    asm("mov.b64 {%0, %1}, %2;" : "=f"(f.x), "=f"(f.y) : "l"(p));
    return f;
}
__device__ __forceinline__ unsigned long long f2fma(unsigned long long a,
                                                    unsigned long long b,
                                                    unsigned long long c) {
    unsigned long long d;
    asm("fma.rn.f32x2 %0, %1, %2, %3;" : "=l"(d) : "l"(a), "l"(b), "l"(c));
    return d;
}

__device__ __forceinline__ uint32_t tf32r(float x) {
    uint32_t r;
    asm("cvt.rna.tf32.f32 %0, %1;" : "=r"(r) : "f"(x));
    return r;
}

// warp mma: D(16x8) += A(16x8,row,tf32) * B(8x8,col,tf32), fp32 accum
__device__ __forceinline__ void mma16n8k8(float* c, const uint32_t* a,
                                          uint32_t b0, uint32_t b1) {
    asm volatile(
        "mma.sync.aligned.m16n8k8.row.col.f32.tf32.tf32.f32 "
        "{%0,%1,%2,%3}, {%4,%5,%6,%7}, {%8,%9}, {%0,%1,%2,%3};"
        : "+f"(c[0]), "+f"(c[1]), "+f"(c[2]), "+f"(c[3])
        : "r"(a[0]), "r"(a[1]), "r"(a[2]), "r"(a[3]), "r"(b0), "r"(b1));
}

// ============================================================
// Kernel A: fused QKV projection, out = tanh(x @ W + b)  (FFMA2)
// ============================================================
__global__ __launch_bounds__(256, 1) void proj_kernel(
    const float* __restrict__ x,
    const float* __restrict__ Wq, const float* __restrict__ bq,
    const float* __restrict__ Wk, const float* __restrict__ bk,
    const float* __restrict__ Wv, const float* __restrict__ bv) {
    extern __shared__ float sm[];
    float* xs = sm;              // 64*128
    float* ws = sm + 64 * 128;   // 32*128

    const float* W;
    const float* bias;
    float* outp;
    if (blockIdx.y == 0)      { W = Wq; bias = bq; outp = g_q; }
    else if (blockIdx.y == 1) { W = Wk; bias = bk; outp = g_k; }
    else                      { W = Wv; bias = bv; outp = g_v; }

    const int tid = threadIdx.x;
    const int rowg = tid >> 4;
    const int colg = tid & 15;
    const int row0 = blockIdx.x * 64;

    {
        const float4* src = reinterpret_cast<const float4*>(x + (size_t)row0 * DD);
        float4* dst = reinterpret_cast<float4*>(xs);
#pragma unroll
        for (int t = 0; t < 8; t++) dst[tid + t * 256] = src[tid + t * 256];
    }

    unsigned long long acc[4][4];
#pragma unroll
    for (int r = 0; r < 4; r++)
#pragma unroll
        for (int c = 0; c < 4; c++) acc[r][c] = 0ull;

#pragma unroll 1
    for (int chunk = 0; chunk < 4; chunk++) {
        const int kk0 = chunk * 32;
        __syncthreads();
        {
            const float4* src = reinterpret_cast<const float4*>(W + (size_t)kk0 * HH);
            float4* dst = reinterpret_cast<float4*>(ws);
#pragma unroll
            for (int t = 0; t < 4; t++) dst[tid + t * 256] = src[tid + t * 256];
        }
        __syncthreads();

#pragma unroll 2
        for (int kkl = 0; kkl < 32; kkl++) {
            const int kk = kk0 + kkl;
            float xv[4];
#pragma unroll
            for (int r = 0; r < 4; r++) xv[r] = xs[(rowg * 4 + r) * DD + kk];
            float4 wa = *reinterpret_cast<const float4*>(ws + kkl * HH + colg * 4);
            float4 wb = *reinterpret_cast<const float4*>(ws + kkl * HH + 64 + colg * 4);
            unsigned long long wp[4];
            wp[0] = *reinterpret_cast<unsigned long long*>(&wa.x);
            wp[1] = *reinterpret_cast<unsigned long long*>(&wa.z);
            wp[2] = *reinterpret_cast<unsigned long long*>(&wb.x);
            wp[3] = *reinterpret_cast<unsigned long long*>(&wb.z);
#pragma unroll
            for (int r = 0; r < 4; r++) {
                unsigned long long xp = pk2(xv[r], xv[r]);
#pragma unroll
                for (int c = 0; c < 4; c++) acc[r][c] = f2fma(xp, wp[c], acc[r][c]);
            }
        }
    }

    float4 ba = *reinterpret_cast<const float4*>(bias + colg * 4);
    float4 bb = *reinterpret_cast<const float4*>(bias + 64 + colg * 4);
#pragma unroll
    for (int r = 0; r < 4; r++) {
        float2 a0 = upk2(acc[r][0]);
        float2 a1 = upk2(acc[r][1]);
        float2 a2 = upk2(acc[r][2]);
        float2 a3 = upk2(acc[r][3]);
        float4 oa, ob;
        oa.x = tanhf(a0.x + ba.x); oa.y = tanhf(a0.y + ba.y);
        oa.z = tanhf(a1.x + ba.z); oa.w = tanhf(a1.y + ba.w);
        ob.x = tanhf(a2.x + bb.x); ob.y = tanhf(a2.y + bb.y);
        ob.z = tanhf(a3.x + bb.z); ob.w = tanhf(a3.y + bb.w);
        float* orow = outp + (size_t)(row0 + rowg * 4 + r) * HH;
        *reinterpret_cast<float4*>(orow + colg * 4) = oa;
        *reinterpret_cast<float4*>(orow + 64 + colg * 4) = ob;
    }
}

// ============================================================
// Kernel B: tf32 mma.sync flash attention, fixed-offset softmax.
// grid 512 (32 b x 16 i-tiles), 256 threads / 8 warps.
// Warp w owns i-rows [w*16, w*16+16).
// smem: Ks[128][132] | Vs[128][132] | Ps[128][132]  (tf32 bits as u32)
// Q fragments persistent in regs; O accumulates in regs across j-tiles
// (fixed-offset softmax: p = mask ? exp(s-40) : 0, normalize at end).
// ============================================================
#define LDW 132
#define TILEW (128 * LDW)          // words per smem tile
#define SMEM_ATT (3 * TILEW * 4)   // bytes

__global__ __launch_bounds__(256, 1) void attn_mma(
    const float* __restrict__ mask, float* __restrict__ out) {
    extern __shared__ uint32_t smw[];
    uint32_t* Ks = smw;
    uint32_t* Vs = smw + TILEW;
    uint32_t* Ps = smw + 2 * TILEW;

    const int tid = threadIdx.x;
    const int lane = tid & 31;
    const int w = tid >> 5;
    const int b = blockIdx.x >> 4;
    const int i0 = (blockIdx.x & 15) << 7;
    const int qp = lane >> 2;   // quad-pair row index 0..7
    const int ql = lane & 3;    // lane within quad 0..3
    const int r0 = w * 16 + qp; // local i-row (also +8)

    // ---- stage Q (tf32) into Ps buffer, coalesced ----
    {
        const float4* src =
            reinterpret_cast<const float4*>(g_q + ((size_t)(b * NN) + i0) * HH);
#pragma unroll
        for (int t = 0; t < 16; t++) {
            const int idx = tid + t * 256;     // 0..4095
            const int row = idx >> 5, c4 = idx & 31;
            float4 v = src[idx];
            uint4 u;
            u.x = tf32r(v.x); u.y = tf32r(v.y); u.z = tf32r(v.z); u.w = tf32r(v.w);
            *reinterpret_cast<uint4*>(Ps + row * LDW + c4 * 4) = u;
        }
    }
    __syncthreads();

    // ---- load persistent Q fragments ----
    uint32_t qa[16][4];
    {
        const uint32_t* qb = Ps + r0 * LDW + ql;
#pragma unroll
        for (int k = 0; k < 16; k++) {
            qa[k][0] = qb[k * 8];
            qa[k][1] = qb[k * 8 + 8 * LDW];
            qa[k][2] = qb[k * 8 + 4];
            qa[k][3] = qb[k * 8 + 4 + 8 * LDW];
        }
    }

    float oa[16][4];
#pragma unroll
    for (int h = 0; h < 16; h++)
#pragma unroll
        for (int c = 0; c < 4; c++) oa[h][c] = 0.0f;
    float ls0 = 0.0f, ls1 = 0.0f;

    const float* mrow0 = mask + ((size_t)(b * NN) + i0 + w * 16 + qp) * NN;
    const float* mrow1 = mrow0 + (size_t)8 * NN;

#pragma unroll 1
    for (int jt = 0; jt < 16; jt++) {
        const int j0 = jt << 7;
        __syncthreads();  // previous PV done with Ks/Vs/Ps

        // ---- K, V tiles -> smem (tf32), coalesced ----
        {
            const float4* ksrc =
                reinterpret_cast<const float4*>(g_k + ((size_t)(b * NN) + j0) * HH);
            const float4* vsrc =
                reinterpret_cast<const float4*>(g_v + ((size_t)(b * NN) + j0) * HH);
#pragma unroll
            for (int t = 0; t < 16; t++) {
                const int idx = tid + t * 256;
                const int row = idx >> 5, c4 = idx & 31;
                float4 kv = ksrc[idx];
                uint4 ku;
                ku.x = tf32r(kv.x); ku.y = tf32r(kv.y);
                ku.z = tf32r(kv.z); ku.w = tf32r(kv.w);
                *reinterpret_cast<uint4*>(Ks + row * LDW + c4 * 4) = ku;
                float4 vv = vsrc[idx];
                uint4 vu;
                vu.x = tf32r(vv.x); vu.y = tf32r(vv.y);
                vu.z = tf32r(vv.z); vu.w = tf32r(vv.w);
                *reinterpret_cast<uint4*>(Vs + row * LDW + c4 * 4) = vu;
            }
        }
        __syncthreads();

        // ---- S = Q K^T, mask, exp, P -> smem ----
        float lp0 = 0.0f, lp1 = 0.0f;
#pragma unroll 1
        for (int nb = 0; nb < 16; nb++) {
            float acc[4] = {0.0f, 0.0f, 0.0f, 0.0f};
            const uint32_t* kb = Ks + (nb * 8 + qp) * LDW + ql;
#pragma unroll
            for (int k = 0; k < 16; k++) {
                uint32_t b0 = kb[k * 8];
                uint32_t b1 = kb[k * 8 + 4];
                mma16n8k8(acc, qa[k], b0, b1);
            }
            const int jcol = j0 + nb * 8 + 2 * ql;
            float2 m0 = __ldg(reinterpret_cast<const float2*>(mrow0 + jcol));
            float2 m1 = __ldg(reinterpret_cast<const float2*>(mrow1 + jcol));
            float p0 = (m0.x != 0.0f) ? __expf(acc[0] - 40.0f) : 0.0f;
            float p1 = (m0.y != 0.0f) ? __expf(acc[1] - 40.0f) : 0.0f;
            float p2 = (m1.x != 0.0f) ? __expf(acc[2] - 40.0f) : 0.0f;
            float p3 = (m1.y != 0.0f) ? __expf(acc[3] - 40.0f) : 0.0f;
            lp0 += p0 + p1;
            lp1 += p2 + p3;
            // store P (tf32 bits) as two 8B writes
            uint32_t* pd0 = Ps + r0 * LDW + nb * 8 + 2 * ql;
            uint32_t* pd1 = pd0 + 8 * LDW;
            uint2 w0; w0.x = tf32r(p0); w0.y = tf32r(p1);
            uint2 w1; w1.x = tf32r(p2); w1.y = tf32r(p3);
            *reinterpret_cast<uint2*>(pd0) = w0;
            *reinterpret_cast<uint2*>(pd1) = w1;
        }
        // reduce row sums across the quad
        lp0 += __shfl_xor_sync(0xffffffffu, lp0, 1);
        lp0 += __shfl_xor_sync(0xffffffffu, lp0, 2);
        lp1 += __shfl_xor_sync(0xffffffffu, lp1, 1);
        lp1 += __shfl_xor_sync(0xffffffffu, lp1, 2);
        ls0 += lp0;
        ls1 += lp1;
        __syncthreads();  // all P written

        // ---- O += P V ----
        const uint32_t* pb = Ps + r0 * LDW + ql;
#pragma unroll 1
        for (int k = 0; k < 16; k++) {
            uint32_t pa[4];
            pa[0] = pb[k * 8];
            pa[1] = pb[k * 8 + 8 * LDW];
            pa[2] = pb[k * 8 + 4];
            pa[3] = pb[k * 8 + 4 + 8 * LDW];
            const uint32_t* vb = Vs + (k * 8 + ql) * LDW + qp;
#pragma unroll
            for (int h = 0; h < 16; h++) {
                uint32_t b0 = vb[h * 8];
                uint32_t b1 = vb[h * 8 + 4 * LDW];
                mma16n8k8(oa[h], pa, b0, b1);
            }
        }
    }

    // ---- epilogue: normalize, store ----
    const float inv0 = 1.0f / ls0;
    const float inv1 = 1.0f / ls1;
    float* orow0 = out + ((size_t)(b * NN) + i0 + w * 16 + qp) * HH + 2 * ql;
    float* orow1 = orow0 + (size_t)8 * HH;
#pragma unroll
    for (int h = 0; h < 16; h++) {
        float2 v0, v1;
        v0.x = oa[h][0] * inv0; v0.y = oa[h][1] * inv0;
        v1.x = oa[h][2] * inv1; v1.y = oa[h][3] * inv1;
        *reinterpret_cast<float2*>(orow0 + h * 8) = v0;
        *reinterpret_cast<float2*>(orow1 + h * 8) = v1;
    }
}

extern "C" void kernel_launch(void* const* d_in, const int* in_sizes, int n_in,
                              void* d_out, int out_size) {
    const float* x    = (const float*)d_in[0];
    const float* mask = (const float*)d_in[1];
    const float* Wv   = (const float*)d_in[2];
    const float* bv   = (const float*)d_in[3];
    const float* Wk   = (const float*)d_in[4];
    const float* bk   = (const float*)d_in[5];
    const float* Wq   = (const float*)d_in[6];
    const float* bq   = (const float*)d_in[7];
    float* out = (float*)d_out;

    cudaFuncSetAttribute(proj_kernel, cudaFuncAttributeMaxDynamicSharedMemorySize,
                         49152);
    cudaFuncSetAttribute(attn_mma, cudaFuncAttributeMaxDynamicSharedMemorySize,
                         SMEM_ATT);

    proj_kernel<<<dim3(1024, 3, 1), 256, 49152>>>(x, Wq, bq, Wk, bk, Wv, bv);
    attn_mma<<<512, 256, SMEM_ATT>>>(mask, out);
}

// round 4
// speedup vs baseline: 2.2697x; 1.0714x over previous
#include <cuda_runtime.h>
#include <cstdint>
#include <cstddef>

#define BB 32
#define NN 2048
#define DD 128
#define HH 128

// Scratch for q/k/v activations (allocation-free rule: static device arrays).
__device__ float g_q[BB * NN * HH];
__device__ float g_k[BB * NN * HH];
__device__ float g_v[BB * NN * HH];

// ---------- packed f32x2 helpers (projection kernel) ----------
__device__ __forceinline__ unsigned long long pk2(float lo, float hi) {
    unsigned long long r;
    asm("mov.b64 %0, {%1, %2};" : "=l"(r) : "f"(lo), "f"(hi));
    return r;
}
__device__ __forceinline__ float2 upk2(unsigned long long p) {
    float2 f;
    asm("mov.b64 {%0, %1}, %2;" : "=f"(f.x), "=f"(f.y) : "l"(p));
    return f;
}
__device__ __forceinline__ unsigned long long f2fma(unsigned long long a,
                                                    unsigned long long b,
                                                    unsigned long long c) {
    unsigned long long d;
    asm("fma.rn.f32x2 %0, %1, %2, %3;" : "=l"(d) : "l"(a), "l"(b), "l"(c));
    return d;
}

__device__ __forceinline__ uint32_t tf32r(float x) {
    uint32_t r;
    asm("cvt.rna.tf32.f32 %0, %1;" : "=r"(r) : "f"(x));
    return r;
}

// warp mma: D(16x8) += A(16x8,row,tf32) * B(8x8,col,tf32), fp32 accum
__device__ __forceinline__ void mma16n8k8(float* c, const uint32_t* a,
                                          uint32_t b0, uint32_t b1) {
    asm volatile(
        "mma.sync.aligned.m16n8k8.row.col.f32.tf32.tf32.f32 "
        "{%0,%1,%2,%3}, {%4,%5,%6,%7}, {%8,%9}, {%0,%1,%2,%3};"
        : "+f"(c[0]), "+f"(c[1]), "+f"(c[2]), "+f"(c[3])
        : "r"(a[0]), "r"(a[1]), "r"(a[2]), "r"(a[3]), "r"(b0), "r"(b1));
}

__device__ __forceinline__ uint32_t smem_u32(const void* p) {
    uint32_t a;
    asm("{ .reg .u64 t; cvta.to.shared.u64 t, %1; cvt.u32.u64 %0, t; }"
        : "=r"(a) : "l"(p));
    return a;
}

#define CP_ASYNC16(dst, src)                                                \
    asm volatile("cp.async.cg.shared.global [%0], [%1], 16;" ::             \
                     "r"(dst), "l"(src) : "memory")
#define CP_COMMIT() asm volatile("cp.async.commit_group;" ::: "memory")
#define CP_WAIT0() asm volatile("cp.async.wait_group 0;" ::: "memory")

// ============================================================
// Kernel A: fused QKV projection, out = tanh(x @ W + b)  (FFMA2)
// Stores tf32-PRE-ROUNDED values so the attention kernel can copy raw bits.
// ============================================================
__global__ __launch_bounds__(256, 1) void proj_kernel(
    const float* __restrict__ x,
    const float* __restrict__ Wq, const float* __restrict__ bq,
    const float* __restrict__ Wk, const float* __restrict__ bk,
    const float* __restrict__ Wv, const float* __restrict__ bv) {
    extern __shared__ float sm[];
    float* xs = sm;              // 64*128
    float* ws = sm + 64 * 128;   // 32*128

    const float* W;
    const float* bias;
    float* outp;
    if (blockIdx.y == 0)      { W = Wq; bias = bq; outp = g_q; }
    else if (blockIdx.y == 1) { W = Wk; bias = bk; outp = g_k; }
    else                      { W = Wv; bias = bv; outp = g_v; }

    const int tid = threadIdx.x;
    const int rowg = tid >> 4;
    const int colg = tid & 15;
    const int row0 = blockIdx.x * 64;

    {
        const float4* src = reinterpret_cast<const float4*>(x + (size_t)row0 * DD);
        float4* dst = reinterpret_cast<float4*>(xs);
#pragma unroll
        for (int t = 0; t < 8; t++) dst[tid + t * 256] = src[tid + t * 256];
    }

    unsigned long long acc[4][4];
#pragma unroll
    for (int r = 0; r < 4; r++)
#pragma unroll
        for (int c = 0; c < 4; c++) acc[r][c] = 0ull;

#pragma unroll 1
    for (int chunk = 0; chunk < 4; chunk++) {
        const int kk0 = chunk * 32;
        __syncthreads();
        {
            const float4* src = reinterpret_cast<const float4*>(W + (size_t)kk0 * HH);
            float4* dst = reinterpret_cast<float4*>(ws);
#pragma unroll
            for (int t = 0; t < 4; t++) dst[tid + t * 256] = src[tid + t * 256];
        }
        __syncthreads();

#pragma unroll 2
        for (int kkl = 0; kkl < 32; kkl++) {
            const int kk = kk0 + kkl;
            float xv[4];
#pragma unroll
            for (int r = 0; r < 4; r++) xv[r] = xs[(rowg * 4 + r) * DD + kk];
            float4 wa = *reinterpret_cast<const float4*>(ws + kkl * HH + colg * 4);
            float4 wb = *reinterpret_cast<const float4*>(ws + kkl * HH + 64 + colg * 4);
            unsigned long long wp[4];
            wp[0] = *reinterpret_cast<unsigned long long*>(&wa.x);
            wp[1] = *reinterpret_cast<unsigned long long*>(&wa.z);
            wp[2] = *reinterpret_cast<unsigned long long*>(&wb.x);
            wp[3] = *reinterpret_cast<unsigned long long*>(&wb.z);
#pragma unroll
            for (int r = 0; r < 4; r++) {
                unsigned long long xp = pk2(xv[r], xv[r]);
#pragma unroll
                for (int c = 0; c < 4; c++) acc[r][c] = f2fma(xp, wp[c], acc[r][c]);
            }
        }
    }

    float4 ba = *reinterpret_cast<const float4*>(bias + colg * 4);
    float4 bb = *reinterpret_cast<const float4*>(bias + 64 + colg * 4);
#pragma unroll
    for (int r = 0; r < 4; r++) {
        float2 a0 = upk2(acc[r][0]);
        float2 a1 = upk2(acc[r][1]);
        float2 a2 = upk2(acc[r][2]);
        float2 a3 = upk2(acc[r][3]);
        float4 oa, ob;
        oa.x = __uint_as_float(tf32r(tanhf(a0.x + ba.x)));
        oa.y = __uint_as_float(tf32r(tanhf(a0.y + ba.y)));
        oa.z = __uint_as_float(tf32r(tanhf(a1.x + ba.z)));
        oa.w = __uint_as_float(tf32r(tanhf(a1.y + ba.w)));
        ob.x = __uint_as_float(tf32r(tanhf(a2.x + bb.x)));
        ob.y = __uint_as_float(tf32r(tanhf(a2.y + bb.y)));
        ob.z = __uint_as_float(tf32r(tanhf(a3.x + bb.z)));
        ob.w = __uint_as_float(tf32r(tanhf(a3.y + bb.w)));
        float* orow = outp + (size_t)(row0 + rowg * 4 + r) * HH;
        *reinterpret_cast<float4*>(orow + colg * 4) = oa;
        *reinterpret_cast<float4*>(orow + 64 + colg * 4) = ob;
    }
}

// ============================================================
// Kernel B: tf32 mma.sync flash attention v2.
//  - k-outer QK with 16 independent accumulator chains (ILP)
//  - P kept in registers; D->A fragment conversion via shfl
//  - cp.async staging (q/k/v pre-rounded by proj); K[jt+1] prefetched
//    during exp+PV, V[jt+1] after PV.
// smem: Qs[128][132] | Ks[128][132] | Vs[128][136]  (u32 words)
// ============================================================
#define QLDW 132
#define VLDW 136
#define KS_OFF (128 * QLDW)
#define VS_OFF (2 * 128 * QLDW)
#define SMEM_ATT ((2 * 128 * QLDW + 128 * VLDW) * 4)

__global__ __launch_bounds__(256, 1) void attn_mma(
    const float* __restrict__ mask, float* __restrict__ out) {
    extern __shared__ uint32_t smw[];
    uint32_t* Qs = smw;
    uint32_t* Ks = smw + KS_OFF;
    uint32_t* Vs = smw + VS_OFF;
    const uint32_t smb = smem_u32(smw);

    const int tid = threadIdx.x;
    const int lane = tid & 31;
    const int w = tid >> 5;
    const int b = blockIdx.x >> 4;
    const int i0 = (blockIdx.x & 15) << 7;
    const int qp = lane >> 2;
    const int ql = lane & 3;
    const int r0 = w * 16 + qp;

    const float* qg = g_q + ((size_t)(b * NN) + i0) * HH;
    const float* kg = g_k + (size_t)(b * NN) * HH;
    const float* vg = g_v + (size_t)(b * NN) * HH;

    // ---- prologue: stage Q, K0, V0 via cp.async ----
#pragma unroll
    for (int t = 0; t < 16; t++) {
        const int idx = tid + t * 256;
        const int row = idx >> 5, c4 = idx & 31;
        CP_ASYNC16(smb + (uint32_t)(row * QLDW + c4 * 4) * 4, qg + idx * 4);
        CP_ASYNC16(smb + (uint32_t)(KS_OFF + row * QLDW + c4 * 4) * 4, kg + idx * 4);
        CP_ASYNC16(smb + (uint32_t)(VS_OFF + row * VLDW + c4 * 4) * 4, vg + idx * 4);
    }
    CP_COMMIT();

    float oa[16][4];
#pragma unroll
    for (int h = 0; h < 16; h++)
#pragma unroll
        for (int c = 0; c < 4; c++) oa[h][c] = 0.0f;
    float ls0 = 0.0f, ls1 = 0.0f;

    const float* mrow0 = mask + ((size_t)(b * NN) + i0 + r0) * NN;
    const float* mrow1 = mrow0 + (size_t)8 * NN;

#pragma unroll 1
    for (int jt = 0; jt < 16; jt++) {
        const int j0 = jt << 7;
        CP_WAIT0();
        __syncthreads();   // K/V tiles for jt are in smem; prior PV done with Vs

        // ---- S = Q K^T : k outer, 16 independent nb chains ----
        float sf[16][4];
#pragma unroll
        for (int nb = 0; nb < 16; nb++)
#pragma unroll
            for (int c = 0; c < 4; c++) sf[nb][c] = 0.0f;

#pragma unroll 4
        for (int k = 0; k < 16; k++) {
            const uint32_t* qb = Qs + r0 * QLDW + k * 8 + ql;
            uint32_t qa[4];
            qa[0] = qb[0];
            qa[1] = qb[8 * QLDW];
            qa[2] = qb[4];
            qa[3] = qb[4 + 8 * QLDW];
#pragma unroll
            for (int nb = 0; nb < 16; nb++) {
                const uint32_t* kb = Ks + (nb * 8 + qp) * QLDW + k * 8 + ql;
                mma16n8k8(sf[nb], qa, kb[0], kb[4]);
            }
        }
        __syncthreads();   // all warps done reading Ks
        if (jt < 15) {
            const float* kn = kg + ((size_t)(j0 + 128)) * HH;
#pragma unroll
            for (int t = 0; t < 16; t++) {
                const int idx = tid + t * 256;
                const int row = idx >> 5, c4 = idx & 31;
                CP_ASYNC16(smb + (uint32_t)(KS_OFF + row * QLDW + c4 * 4) * 4,
                           kn + idx * 4);
            }
            CP_COMMIT();
        }

        // ---- mask + exp + D->A fragment conversion (registers only) ----
        float nls0 = 0.0f, nls1 = 0.0f;
        uint32_t pa[16][4];
        const int L0 = qp * 4 + (ql >> 1);
        const bool odd = (ql & 1);
#pragma unroll
        for (int nb = 0; nb < 16; nb++) {
            const int jcol = j0 + nb * 8 + 2 * ql;
            float2 m0 = __ldg(reinterpret_cast<const float2*>(mrow0 + jcol));
            float2 m1 = __ldg(reinterpret_cast<const float2*>(mrow1 + jcol));
            uint32_t u0 = (m0.x != 0.0f) ? tf32r(__expf(sf[nb][0] - 40.0f)) : 0u;
            uint32_t u1 = (m0.y != 0.0f) ? tf32r(__expf(sf[nb][1] - 40.0f)) : 0u;
            uint32_t u2 = (m1.x != 0.0f) ? tf32r(__expf(sf[nb][2] - 40.0f)) : 0u;
            uint32_t u3 = (m1.y != 0.0f) ? tf32r(__expf(sf[nb][3] - 40.0f)) : 0u;
            nls0 += __uint_as_float(u0) + __uint_as_float(u1);
            nls1 += __uint_as_float(u2) + __uint_as_float(u3);
            uint32_t t00 = __shfl_sync(0xffffffffu, u0, L0);
            uint32_t t01 = __shfl_sync(0xffffffffu, u1, L0);
            uint32_t t10 = __shfl_sync(0xffffffffu, u2, L0);
            uint32_t t11 = __shfl_sync(0xffffffffu, u3, L0);
            uint32_t t20 = __shfl_sync(0xffffffffu, u0, L0 + 2);
            uint32_t t21 = __shfl_sync(0xffffffffu, u1, L0 + 2);
            uint32_t t30 = __shfl_sync(0xffffffffu, u2, L0 + 2);
            uint32_t t31 = __shfl_sync(0xffffffffu, u3, L0 + 2);
            pa[nb][0] = odd ? t01 : t00;
            pa[nb][1] = odd ? t11 : t10;
            pa[nb][2] = odd ? t21 : t20;
            pa[nb][3] = odd ? t31 : t30;
        }
        nls0 += __shfl_xor_sync(0xffffffffu, nls0, 1);
        nls0 += __shfl_xor_sync(0xffffffffu, nls0, 2);
        nls1 += __shfl_xor_sync(0xffffffffu, nls1, 1);
        nls1 += __shfl_xor_sync(0xffffffffu, nls1, 2);
        ls0 += nls0;
        ls1 += nls1;

        // ---- O += P V : h inner, 16 independent chains ----
#pragma unroll 4
        for (int k = 0; k < 16; k++) {
            const uint32_t* vb = Vs + (k * 8 + ql) * VLDW + qp;
#pragma unroll
            for (int h = 0; h < 16; h++) {
                mma16n8k8(oa[h], pa[k], vb[h * 8], vb[h * 8 + 4 * VLDW]);
            }
        }
        __syncthreads();   // all warps done reading Vs
        if (jt < 15) {
            const float* vn = vg + ((size_t)(j0 + 128)) * HH;
#pragma unroll
            for (int t = 0; t < 16; t++) {
                const int idx = tid + t * 256;
                const int row = idx >> 5, c4 = idx & 31;
                CP_ASYNC16(smb + (uint32_t)(VS_OFF + row * VLDW + c4 * 4) * 4,
                           vn + idx * 4);
            }
            CP_COMMIT();
        }
    }

    // ---- epilogue: normalize, store ----
    const float inv0 = 1.0f / ls0;
    const float inv1 = 1.0f / ls1;
    float* orow0 = out + ((size_t)(b * NN) + i0 + r0) * HH + 2 * ql;
    float* orow1 = orow0 + (size_t)8 * HH;
#pragma unroll
    for (int h = 0; h < 16; h++) {
        float2 v0, v1;
        v0.x = oa[h][0] * inv0; v0.y = oa[h][1] * inv0;
        v1.x = oa[h][2] * inv1; v1.y = oa[h][3] * inv1;
        *reinterpret_cast<float2*>(orow0 + h * 8) = v0;
        *reinterpret_cast<float2*>(orow1 + h * 8) = v1;
    }
}

extern "C" void kernel_launch(void* const* d_in, const int* in_sizes, int n_in,
                              void* d_out, int out_size) {
    const float* x    = (const float*)d_in[0];
    const float* mask = (const float*)d_in[1];
    const float* Wv   = (const float*)d_in[2];
    const float* bv   = (const float*)d_in[3];
    const float* Wk   = (const float*)d_in[4];
    const float* bk   = (const float*)d_in[5];
    const float* Wq   = (const float*)d_in[6];
    const float* bq   = (const float*)d_in[7];
    float* out = (float*)d_out;

    cudaFuncSetAttribute(proj_kernel, cudaFuncAttributeMaxDynamicSharedMemorySize,
                         49152);
    cudaFuncSetAttribute(attn_mma, cudaFuncAttributeMaxDynamicSharedMemorySize,
                         SMEM_ATT);

    proj_kernel<<<dim3(1024, 3, 1), 256, 49152>>>(x, Wq, bq, Wk, bk, Wv, bv);
    attn_mma<<<512, 256, SMEM_ATT>>>(mask, out);
}